// round 6
// baseline (speedup 1.0000x reference)
#include <cuda_runtime.h>
#include <cuda_bf16.h>
#include <stdint.h>
#include <math.h>

#define Bb 4
#define Ss 2048
#define Ee 1024
#define Hh 16
#define Dd 64
#define FFf 4096
#define NT (Bb*Ss)          // 8192 tokens
#define HALF_WIN 128

// ------------------------- scratch (device globals; no allocations) -------------------------
__device__ float g_h   [NT * Ee];
__device__ float g_qkv [NT * 3 * Ee];
__device__ float g_q   [Bb * Hh * Ss * Dd];
__device__ float g_k   [Bb * Hh * Ss * Dd];
__device__ float g_v   [Bb * Hh * Ss * Dd];
__device__ float g_attn[NT * Ee];
__device__ float g_x1  [NT * Ee];
__device__ float g_gate[NT * FFf];

// ------------------------- block reduce helper -------------------------
__device__ __forceinline__ float blockReduceSum(float v, float* red) {
    #pragma unroll
    for (int o = 16; o > 0; o >>= 1) v += __shfl_xor_sync(0xffffffffu, v, o);
    if ((threadIdx.x & 31) == 0) red[threadIdx.x >> 5] = v;
    __syncthreads();
    float t = 0.f;
    #pragma unroll
    for (int i = 0; i < 8; i++) t += red[i];
    __syncthreads();
    return t;
}

// ------------------------- LayerNorm: one block per token -------------------------
__global__ __launch_bounds__(256) void ln_kernel(
    const float* __restrict__ x, const float* __restrict__ gamma,
    const float* __restrict__ beta, float* __restrict__ out)
{
    __shared__ float red[8];
    const int t = blockIdx.x;
    const int tid = threadIdx.x;
    const float4 v = ((const float4*)(x + (size_t)t * Ee))[tid];

    float s = v.x + v.y + v.z + v.w;
    s = blockReduceSum(s, red);
    const float mu = s * (1.0f / Ee);

    float dx = (v.x-mu)*(v.x-mu) + (v.y-mu)*(v.y-mu) + (v.z-mu)*(v.z-mu) + (v.w-mu)*(v.w-mu);
    dx = blockReduceSum(dx, red);
    const float inv = rsqrtf(dx * (1.0f / Ee) + 1e-5f);

    const float4 g4 = ((const float4*)gamma)[tid];
    const float4 b4 = ((const float4*)beta)[tid];
    float4 r;
    r.x = (v.x - mu) * inv * g4.x + b4.x;
    r.y = (v.y - mu) * inv * g4.y + b4.y;
    r.z = (v.z - mu) * inv * g4.z + b4.z;
    r.w = (v.w - mu) * inv * g4.w + b4.w;
    ((float4*)(out + (size_t)t * Ee))[tid] = r;
}

// ------------------------- tensor-core GEMM (bf16x3 split) -------------------------
// Block tile 128x128x32, 8 warps, warp tile 32x64, mma.m16n8k16.bf16, fp32 accum.
#define LDAU 20                       // uint32 (bf16x2) stride per 128-row; 80B
#define STGU (128 * LDAU)             // 2560 uints per operand tile per stage

__device__ __forceinline__ uint32_t pack_bf2(__nv_bfloat16 a, __nv_bfloat16 b) {
    __nv_bfloat162 t; t.x = a; t.y = b;
    return *reinterpret_cast<uint32_t*>(&t);
}

__device__ __forceinline__ void ldsm4(uint32_t r[4], const uint32_t* p) {
    uint32_t addr = (uint32_t)__cvta_generic_to_shared(p);
    asm volatile("ldmatrix.sync.aligned.m8n8.x4.shared.b16 {%0,%1,%2,%3}, [%4];"
                 : "=r"(r[0]), "=r"(r[1]), "=r"(r[2]), "=r"(r[3]) : "r"(addr));
}

__device__ __forceinline__ void mma16816(float c[4], const uint32_t a[4],
                                         uint32_t b0, uint32_t b1) {
    asm volatile("mma.sync.aligned.m16n8k16.row.col.f32.bf16.bf16.f32 "
                 "{%0,%1,%2,%3}, {%4,%5,%6,%7}, {%8,%9}, {%0,%1,%2,%3};"
                 : "+f"(c[0]), "+f"(c[1]), "+f"(c[2]), "+f"(c[3])
                 : "r"(a[0]), "r"(a[1]), "r"(a[2]), "r"(a[3]), "r"(b0), "r"(b1));
}

// global -> registers
__device__ __forceinline__ void gemm_load(
    float4 (&aReg)[4], float4 (&bReg)[4],
    const float* __restrict__ Ag, const float* __restrict__ Gg,
    int K, int N, int k0, int ar0, int ac, int bk0, int bn)
{
    #pragma unroll
    for (int i = 0; i < 4; i++) {
        aReg[i] = *(const float4*)(Ag + (size_t)(ar0 + 32 * i) * K + k0 + ac);
        bReg[i] = *(const float4*)(Gg + (size_t)(k0 + bk0 + 8 * i) * N + bn);
    }
}

// registers -> shared (hi/lo bf16 split)
__device__ __forceinline__ void gemm_store_stage(
    const float4 (&aReg)[4], const float4 (&bReg)[4],
    uint32_t* __restrict__ sAhS, uint32_t* __restrict__ sAlS,
    __nv_bfloat16* __restrict__ sBhS, __nv_bfloat16* __restrict__ sBlS,
    int ar0, int ac, int bk0, int bn)
{
    #pragma unroll
    for (int i = 0; i < 4; i++) {
        float xa0 = aReg[i].x, xa1 = aReg[i].y, xa2 = aReg[i].z, xa3 = aReg[i].w;
        __nv_bfloat16 h0 = __float2bfloat16_rn(xa0);
        __nv_bfloat16 h1 = __float2bfloat16_rn(xa1);
        __nv_bfloat16 h2 = __float2bfloat16_rn(xa2);
        __nv_bfloat16 h3 = __float2bfloat16_rn(xa3);
        __nv_bfloat16 l0 = __float2bfloat16_rn(xa0 - __bfloat162float(h0));
        __nv_bfloat16 l1 = __float2bfloat16_rn(xa1 - __bfloat162float(h1));
        __nv_bfloat16 l2 = __float2bfloat16_rn(xa2 - __bfloat162float(h2));
        __nv_bfloat16 l3 = __float2bfloat16_rn(xa3 - __bfloat162float(h3));
        const int idxA = (ar0 + 32 * i) * LDAU + (ac >> 1);
        sAhS[idxA]     = pack_bf2(h0, h1);
        sAhS[idxA + 1] = pack_bf2(h2, h3);
        sAlS[idxA]     = pack_bf2(l0, l1);
        sAlS[idxA + 1] = pack_bf2(l2, l3);

        float xb0 = bReg[i].x, xb1 = bReg[i].y, xb2 = bReg[i].z, xb3 = bReg[i].w;
        const int krow = bk0 + 8 * i;
        {
            __nv_bfloat16 hh = __float2bfloat16_rn(xb0);
            sBhS[(bn + 0) * (2 * LDAU) + krow] = hh;
            sBlS[(bn + 0) * (2 * LDAU) + krow] = __float2bfloat16_rn(xb0 - __bfloat162float(hh));
        }
        {
            __nv_bfloat16 hh = __float2bfloat16_rn(xb1);
            sBhS[(bn + 1) * (2 * LDAU) + krow] = hh;
            sBlS[(bn + 1) * (2 * LDAU) + krow] = __float2bfloat16_rn(xb1 - __bfloat162float(hh));
        }
        {
            __nv_bfloat16 hh = __float2bfloat16_rn(xb2);
            sBhS[(bn + 2) * (2 * LDAU) + krow] = hh;
            sBlS[(bn + 2) * (2 * LDAU) + krow] = __float2bfloat16_rn(xb2 - __bfloat162float(hh));
        }
        {
            __nv_bfloat16 hh = __float2bfloat16_rn(xb3);
            sBhS[(bn + 3) * (2 * LDAU) + krow] = hh;
            sBlS[(bn + 3) * (2 * LDAU) + krow] = __float2bfloat16_rn(xb3 - __bfloat162float(hh));
        }
    }
}

// shared -> fragments -> mma (3 passes: Ah*Bh, Ah*Bl, Al*Bh)
__device__ __forceinline__ void gemm_compute_stage(
    float (&acc)[2][8][4],
    const uint32_t* __restrict__ sAhS, const uint32_t* __restrict__ sAlS,
    const uint32_t* __restrict__ sBhS, const uint32_t* __restrict__ sBlS,
    int wm, int wn, int mrow, int koff)
{
    #pragma unroll
    for (int ks = 0; ks < 2; ks++) {
        uint32_t rAH[2][4];
        uint32_t rAL[2][4];
        uint32_t rBH[4][4];
        uint32_t rBL[4][4];
        #pragma unroll
        for (int mt = 0; mt < 2; mt++) {
            const int idx = (wm + mt * 16 + mrow) * LDAU + ks * 8 + koff;
            ldsm4(rAH[mt], sAhS + idx);
            ldsm4(rAL[mt], sAlS + idx);
        }
        #pragma unroll
        for (int p = 0; p < 4; p++) {
            const int idx = (wn + p * 16 + mrow) * LDAU + ks * 8 + koff;
            ldsm4(rBH[p], sBhS + idx);
            ldsm4(rBL[p], sBlS + idx);
        }
        #pragma unroll
        for (int mt = 0; mt < 2; mt++) {
            #pragma unroll
            for (int nt = 0; nt < 8; nt++) {
                const int p = nt >> 1;
                const int s = nt & 1;
                mma16816(acc[mt][nt], rAH[mt], rBH[p][s], rBH[p][s + 2]);
                mma16816(acc[mt][nt], rAH[mt], rBL[p][s], rBL[p][s + 2]);
                mma16816(acc[mt][nt], rAL[mt], rBH[p][s], rBH[p][s + 2]);
            }
        }
    }
}

// MODE 0: C = A*W + bias
// MODE 1: C = extra + A*W + bias
// MODE 2: C = gelu(A*W + bias)
// MODE 3: C = (A*W + bias) * extra   (extra may alias C)
template<int MODE>
__global__ __launch_bounds__(256) void mma_gemm(
    const float* __restrict__ A, const float* __restrict__ Wt,
    const float* __restrict__ bias, const float* __restrict__ extra,
    float* __restrict__ C, int M, int N, int K)
{
    extern __shared__ uint32_t sm_u[];
    uint32_t* sAh = sm_u;               // [2][STGU]
    uint32_t* sAl = sm_u + 2 * STGU;
    uint32_t* sBh = sm_u + 4 * STGU;
    uint32_t* sBl = sm_u + 6 * STGU;

    const int tid  = threadIdx.x;
    const int lane = tid & 31;
    const int warp = tid >> 5;
    const int wm   = (warp & 3) * 32;   // warp M offset
    const int wn   = (warp >> 2) * 64;  // warp N offset
    const int bx   = blockIdx.x, by = blockIdx.y;

    float acc[2][8][4];
    #pragma unroll
    for (int i = 0; i < 2; i++)
        #pragma unroll
        for (int j = 0; j < 8; j++)
            #pragma unroll
            for (int q = 0; q < 4; q++) acc[i][j][q] = 0.f;

    const int ar0 = tid >> 3;           // A row 0..31 (+32*i)
    const int ac  = (tid & 7) * 4;      // A k 0..28
    const int bk0 = tid >> 5;           // B k 0..7 (+8*i)
    const int bn  = (tid & 31) * 4;     // B n 0..124

    const float* Ag = A  + (size_t)(by * 128) * K;
    const float* Gg = Wt + bx * 128;

    const int mrow = (lane & 7) + ((lane >> 3) & 1) * 8;
    const int koff = (lane >> 4) * 4;

    float4 aReg[4], bReg[4];

    gemm_load(aReg, bReg, Ag, Gg, K, N, 0, ar0, ac, bk0, bn);
    gemm_store_stage(aReg, bReg, sAh, sAl,
                     (__nv_bfloat16*)sBh, (__nv_bfloat16*)sBl, ar0, ac, bk0, bn);
    __syncthreads();

    const int nIter = K >> 5;
    for (int it = 0; it < nIter; ++it) {
        const int st = it & 1;
        const bool more = (it + 1 < nIter);
        if (more)
            gemm_load(aReg, bReg, Ag, Gg, K, N, (it + 1) << 5, ar0, ac, bk0, bn);
        gemm_compute_stage(acc,
                           sAh + st * STGU, sAl + st * STGU,
                           sBh + st * STGU, sBl + st * STGU,
                           wm, wn, mrow, koff);
        if (more) {
            const int st2 = (it + 1) & 1;
            gemm_store_stage(aReg, bReg,
                             sAh + st2 * STGU, sAl + st2 * STGU,
                             (__nv_bfloat16*)(sBh + st2 * STGU),
                             (__nv_bfloat16*)(sBl + st2 * STGU),
                             ar0, ac, bk0, bn);
        }
        __syncthreads();
    }

    // ---- epilogue ----
    const int g  = lane >> 2;
    const int tg = lane & 3;
    #pragma unroll
    for (int mt = 0; mt < 2; mt++) {
        #pragma unroll
        for (int nt = 0; nt < 8; nt++) {
            const int col = bx * 128 + wn + nt * 8 + tg * 2;
            const float2 bi = *(const float2*)(bias + col);
            #pragma unroll
            for (int hf = 0; hf < 2; hf++) {
                const int row = by * 128 + wm + mt * 16 + g + hf * 8;
                const size_t off = (size_t)row * N + col;
                float2 r;
                r.x = acc[mt][nt][hf * 2 + 0] + bi.x;
                r.y = acc[mt][nt][hf * 2 + 1] + bi.y;
                if (MODE == 1) {
                    const float2 e = *(const float2*)(extra + off);
                    r.x += e.x; r.y += e.y;
                }
                if (MODE == 2) {
                    r.x = r.x * normcdff(r.x);
                    r.y = r.y * normcdff(r.y);
                }
                if (MODE == 3) {
                    const float2 e = *(const float2*)(extra + off);
                    r.x *= e.x; r.y *= e.y;
                }
                *(float2*)(C + off) = r;
            }
        }
    }
}

// ------------------------- RoPE + split QKV -> [B,H,S,D] -------------------------
__global__ void rope_split_kernel(
    const float* __restrict__ qkv,
    float* __restrict__ Q, float* __restrict__ K, float* __restrict__ V)
{
    const int idx = blockIdx.x * blockDim.x + threadIdx.x;
    const int total = Bb * Hh * Ss * 32;
    if (idx >= total) return;
    const int dp = idx & 31;
    const int t  = idx >> 5;
    const int s  = t & (Ss - 1);
    const int bh = t >> 11;
    const int h  = bh & (Hh - 1);
    const int b  = bh >> 4;

    const float* base = qkv + (size_t)(b * Ss + s) * (3 * Ee) + h * Dd;
    const float q1 = base[dp],          q2 = base[dp + 32];
    const float k1 = base[Ee + dp],     k2 = base[Ee + dp + 32];
    const float v1 = base[2*Ee + dp],   v2 = base[2*Ee + dp + 32];

    const float inv = (float)exp(-(double)(2 * dp) / 64.0 * log(10000.0));
    const float ang = (float)s * inv;
    float sn, cs;
    sincosf(ang, &sn, &cs);

    const size_t o = ((size_t)bh * Ss + s) * Dd + dp;
    Q[o]      = q1 * cs - q2 * sn;
    Q[o + 32] = q2 * cs + q1 * sn;
    K[o]      = k1 * cs - k2 * sn;
    K[o + 32] = k2 * cs + k1 * sn;
    V[o]      = v1;
    V[o + 32] = v2;
}

// ------------------------- windowed flash attention -------------------------
__global__ __launch_bounds__(256) void attn_kernel(
    const float* __restrict__ Qg, const float* __restrict__ Kg,
    const float* __restrict__ Vg, float* __restrict__ AO)
{
    extern __shared__ float sm[];
    float* QsT = sm;                 // [d][q]
    float* Ks  = sm + 64 * 68;       // [key][d]
    float* Vs  = Ks + 64 * 68;       // [key][d]
    float* SsT = Vs + 64 * 68;       // [key][q]

    const int tid = threadIdx.x;
    const int q0  = blockIdx.x * 64;
    const int bh  = blockIdx.y;
    const int b   = bh >> 4;
    const int h   = bh & (Hh - 1);
    const float* Qb = Qg + (size_t)bh * Ss * Dd;
    const float* Kb = Kg + (size_t)bh * Ss * Dd;
    const float* Vb = Vg + (size_t)bh * Ss * Dd;

    for (int p = tid; p < 1024; p += 256) {
        const int qr = p >> 4, d4 = (p & 15) << 2;
        const float4 v = *(const float4*)(Qb + (size_t)(q0 + qr) * Dd + d4);
        QsT[(d4+0)*68 + qr] = v.x;
        QsT[(d4+1)*68 + qr] = v.y;
        QsT[(d4+2)*68 + qr] = v.z;
        QsT[(d4+3)*68 + qr] = v.w;
    }

    const int ckey = tid >> 2;
    const int crg  = (tid & 3) << 4;
    const int srow = tid >> 2;
    const int sd0  = (tid & 3) << 4;

    float m = -1e30f, l = 0.f;
    float oacc[16];
    #pragma unroll
    for (int i = 0; i < 16; i++) oacc[i] = 0.f;

    __syncthreads();

    for (int c = 0; c < 5; c++) {
        const int kc0 = q0 - HALF_WIN + c * 64;
        for (int p = tid; p < 1024; p += 256) {
            const int kr = p >> 4, d4 = (p & 15) << 2;
            const int kg = kc0 + kr;
            float4 kv = make_float4(0.f, 0.f, 0.f, 0.f), vv = kv;
            if (kg >= 0 && kg < Ss) {
                kv = *(const float4*)(Kb + (size_t)kg * Dd + d4);
                vv = *(const float4*)(Vb + (size_t)kg * Dd + d4);
            }
            *(float4*)&Ks[kr * 68 + d4] = kv;
            *(float4*)&Vs[kr * 68 + d4] = vv;
        }
        __syncthreads();

        float sc[16];
        #pragma unroll
        for (int i = 0; i < 16; i++) sc[i] = 0.f;
        #pragma unroll 8
        for (int d = 0; d < 64; d++) {
            const float kval = Ks[ckey * 68 + d];
            const float4 qa = *(const float4*)&QsT[d * 68 + crg];
            const float4 qb2 = *(const float4*)&QsT[d * 68 + crg + 4];
            const float4 qc = *(const float4*)&QsT[d * 68 + crg + 8];
            const float4 qd = *(const float4*)&QsT[d * 68 + crg + 12];
            sc[0]  += kval * qa.x;  sc[1]  += kval * qa.y;
            sc[2]  += kval * qa.z;  sc[3]  += kval * qa.w;
            sc[4]  += kval * qb2.x; sc[5]  += kval * qb2.y;
            sc[6]  += kval * qb2.z; sc[7]  += kval * qb2.w;
            sc[8]  += kval * qc.x;  sc[9]  += kval * qc.y;
            sc[10] += kval * qc.z;  sc[11] += kval * qc.w;
            sc[12] += kval * qd.x;  sc[13] += kval * qd.y;
            sc[14] += kval * qd.z;  sc[15] += kval * qd.w;
        }
        const int kg = kc0 + ckey;
        const bool kvalid = (kg >= 0 && kg < Ss);
        #pragma unroll
        for (int i = 0; i < 16; i++) {
            const int qg = q0 + crg + i;
            const bool ok = kvalid && (abs(qg - kg) <= HALF_WIN);
            SsT[ckey * 68 + crg + i] = ok ? sc[i] * 0.125f : -1e9f;
        }
        __syncthreads();

        float cmax = -1e30f;
        #pragma unroll 8
        for (int j = 0; j < 64; j++) cmax = fmaxf(cmax, SsT[j * 68 + srow]);
        if (cmax > -1e8f) {
            const float mnew = fmaxf(m, cmax);
            const float corr = __expf(m - mnew);
            m = mnew;
            l *= corr;
            #pragma unroll
            for (int i = 0; i < 16; i++) oacc[i] *= corr;
            #pragma unroll 4
            for (int j = 0; j < 64; j++) {
                const float p = __expf(SsT[j * 68 + srow] - m);
                l += p;
                const float4 v0 = *(const float4*)&Vs[j * 68 + sd0];
                const float4 v1 = *(const float4*)&Vs[j * 68 + sd0 + 4];
                const float4 v2 = *(const float4*)&Vs[j * 68 + sd0 + 8];
                const float4 v3 = *(const float4*)&Vs[j * 68 + sd0 + 12];
                oacc[0]  += p * v0.x; oacc[1]  += p * v0.y;
                oacc[2]  += p * v0.z; oacc[3]  += p * v0.w;
                oacc[4]  += p * v1.x; oacc[5]  += p * v1.y;
                oacc[6]  += p * v1.z; oacc[7]  += p * v1.w;
                oacc[8]  += p * v2.x; oacc[9]  += p * v2.y;
                oacc[10] += p * v2.z; oacc[11] += p * v2.w;
                oacc[12] += p * v3.x; oacc[13] += p * v3.y;
                oacc[14] += p * v3.z; oacc[15] += p * v3.w;
            }
        }
        __syncthreads();
    }

    const float inv = 1.0f / l;
    float* outp = AO + (size_t)(b * Ss + q0 + srow) * Ee + h * Dd + sd0;
    #pragma unroll
    for (int gq = 0; gq < 4; gq++) {
        float4 r;
        r.x = oacc[gq*4+0] * inv;
        r.y = oacc[gq*4+1] * inv;
        r.z = oacc[gq*4+2] * inv;
        r.w = oacc[gq*4+3] * inv;
        *(float4*)(outp + gq * 4) = r;
    }
}

// ------------------------- launch -------------------------
extern "C" void kernel_launch(void* const* d_in, const int* in_sizes, int n_in,
                              void* d_out, int out_size)
{
    (void)in_sizes; (void)n_in; (void)out_size;
    const float* src    = (const float*)d_in[0];
    const float* Wqkv   = (const float*)d_in[1];
    const float* bqkv   = (const float*)d_in[2];
    const float* Wout   = (const float*)d_in[3];
    const float* bout   = (const float*)d_in[4];
    const float* gamma1 = (const float*)d_in[5];
    const float* beta1  = (const float*)d_in[6];
    const float* gamma2 = (const float*)d_in[7];
    const float* beta2  = (const float*)d_in[8];
    const float* Wg     = (const float*)d_in[9];
    const float* bg     = (const float*)d_in[10];
    const float* Wv     = (const float*)d_in[11];
    const float* bv     = (const float*)d_in[12];
    const float* Wo     = (const float*)d_in[13];
    const float* bo     = (const float*)d_in[14];

    float *h, *qkv, *q, *k, *v, *attn, *x1, *gate;
    cudaGetSymbolAddress((void**)&h,    g_h);
    cudaGetSymbolAddress((void**)&qkv,  g_qkv);
    cudaGetSymbolAddress((void**)&q,    g_q);
    cudaGetSymbolAddress((void**)&k,    g_k);
    cudaGetSymbolAddress((void**)&v,    g_v);
    cudaGetSymbolAddress((void**)&attn, g_attn);
    cudaGetSymbolAddress((void**)&x1,   g_x1);
    cudaGetSymbolAddress((void**)&gate, g_gate);

    const int ATTN_SMEM = 4 * 64 * 68 * 4;  // 69632 B
    cudaFuncSetAttribute(attn_kernel, cudaFuncAttributeMaxDynamicSharedMemorySize, ATTN_SMEM);
    const int GEMM_SMEM = 8 * STGU * 4;     // 81920 B
    cudaFuncSetAttribute(mma_gemm<0>, cudaFuncAttributeMaxDynamicSharedMemorySize, GEMM_SMEM);
    cudaFuncSetAttribute(mma_gemm<1>, cudaFuncAttributeMaxDynamicSharedMemorySize, GEMM_SMEM);
    cudaFuncSetAttribute(mma_gemm<2>, cudaFuncAttributeMaxDynamicSharedMemorySize, GEMM_SMEM);
    cudaFuncSetAttribute(mma_gemm<3>, cudaFuncAttributeMaxDynamicSharedMemorySize, GEMM_SMEM);

    // 1) h1 = LN(src)
    ln_kernel<<<NT, 256>>>(src, gamma1, beta1, h);

    // 2) qkv = h1 @ Wqkv + bqkv
    mma_gemm<0><<<dim3(3 * Ee / 128, NT / 128), 256, GEMM_SMEM>>>(h, Wqkv, bqkv, nullptr, qkv, NT, 3 * Ee, Ee);

    // 3) RoPE + split to [B,H,S,D]
    {
        const int total = Bb * Hh * Ss * 32;
        rope_split_kernel<<<(total + 255) / 256, 256>>>(qkv, q, k, v);
    }

    // 4) windowed attention -> attn [NT, E]
    attn_kernel<<<dim3(Ss / 64, Bb * Hh), 256, ATTN_SMEM>>>(q, k, v, attn);

    // 5) x1 = src + attn @ Wout + bout
    mma_gemm<1><<<dim3(Ee / 128, NT / 128), 256, GEMM_SMEM>>>(attn, Wout, bout, src, x1, NT, Ee, Ee);

    // 6) h2 = LN(x1)
    ln_kernel<<<NT, 256>>>(x1, gamma2, beta2, h);

    // 7) gate = gelu(h2 @ Wg + bg)
    mma_gemm<2><<<dim3(FFf / 128, NT / 128), 256, GEMM_SMEM>>>(h, Wg, bg, nullptr, gate, NT, FFf, Ee);

    // 8) gate = (h2 @ Wv + bv) * gate
    mma_gemm<3><<<dim3(FFf / 128, NT / 128), 256, GEMM_SMEM>>>(h, Wv, bv, gate, gate, NT, FFf, Ee);

    // 9) out = x1 + gate @ Wo + bo
    mma_gemm<1><<<dim3(Ee / 128, NT / 128), 256, GEMM_SMEM>>>(gate, Wo, bo, x1, (float*)d_out, NT, Ee, FFf);
}

// round 12
// speedup vs baseline: 1.7322x; 1.7322x over previous
#include <cuda_runtime.h>
#include <cuda_bf16.h>
#include <stdint.h>
#include <math.h>

#define Bb 4
#define Ss 2048
#define Ee 1024
#define Hh 16
#define Dd 64
#define FFf 4096
#define NT (Bb*Ss)
#define HALF_WIN 128

// ------------------------- scratch (device globals) -------------------------
__device__ float g_qkv [NT * 3 * Ee];
__device__ float g_q   [Bb * Hh * Ss * Dd];
__device__ float g_k   [Bb * Hh * Ss * Dd];
__device__ float g_v   [Bb * Hh * Ss * Dd];
__device__ float g_x1  [NT * Ee];
__device__ float g_gelu[NT * FFf];

__device__ __nv_bfloat16 g_hH   [NT * Ee];
__device__ __nv_bfloat16 g_hL   [NT * Ee];
__device__ __nv_bfloat16 g_attnH[NT * Ee];
__device__ __nv_bfloat16 g_attnL[NT * Ee];
__device__ __nv_bfloat16 g_gateH[NT * FFf];
__device__ __nv_bfloat16 g_gateL[NT * FFf];

// transposed + split weights: WT[N,K]
__device__ __nv_bfloat16 g_WqkvTh[3 * Ee * Ee];
__device__ __nv_bfloat16 g_WqkvTl[3 * Ee * Ee];
__device__ __nv_bfloat16 g_WoutTh[Ee * Ee];
__device__ __nv_bfloat16 g_WoutTl[Ee * Ee];
__device__ __nv_bfloat16 g_WgTh  [FFf * Ee];
__device__ __nv_bfloat16 g_WgTl  [FFf * Ee];
__device__ __nv_bfloat16 g_WvTh  [FFf * Ee];
__device__ __nv_bfloat16 g_WvTl  [FFf * Ee];
__device__ __nv_bfloat16 g_WoTh  [Ee * FFf];
__device__ __nv_bfloat16 g_WoTl  [Ee * FFf];

// ------------------------- small helpers -------------------------
__device__ __forceinline__ float blockReduceSum(float v, float* red) {
    #pragma unroll
    for (int o = 16; o > 0; o >>= 1) v += __shfl_xor_sync(0xffffffffu, v, o);
    if ((threadIdx.x & 31) == 0) red[threadIdx.x >> 5] = v;
    __syncthreads();
    float t = 0.f;
    #pragma unroll
    for (int i = 0; i < 8; i++) t += red[i];
    __syncthreads();
    return t;
}

__device__ __forceinline__ void split_bf16(float v, __nv_bfloat16& h, __nv_bfloat16& l) {
    h = __float2bfloat16_rn(v);
    l = __float2bfloat16_rn(v - __bfloat162float(h));
}

// ------------------------- weight transpose + hi/lo split -------------------------
// W[K,N] fp32 row-major -> WTh/WTl [N,K] bf16 row-major
__global__ __launch_bounds__(256) void wsplit_kernel(
    const float* __restrict__ W, __nv_bfloat16* __restrict__ WTh,
    __nv_bfloat16* __restrict__ WTl, int K, int N)
{
    __shared__ float tile[32][33];
    const int n0 = blockIdx.x * 32;
    const int k0 = blockIdx.y * 32;
    const int tx = threadIdx.x & 31;
    const int ty = threadIdx.x >> 5;   // 0..7
    for (int r = ty; r < 32; r += 8)
        tile[r][tx] = W[(size_t)(k0 + r) * N + n0 + tx];
    __syncthreads();
    for (int r = ty; r < 32; r += 8) {
        const float v = tile[tx][r];   // W[k0+tx][n0+r]
        __nv_bfloat16 h, l;
        split_bf16(v, h, l);
        const size_t o = (size_t)(n0 + r) * K + k0 + tx;
        WTh[o] = h;
        WTl[o] = l;
    }
}

// ------------------------- LayerNorm (writes hi/lo bf16) -------------------------
__global__ __launch_bounds__(256) void ln_kernel(
    const float* __restrict__ x, const float* __restrict__ gamma,
    const float* __restrict__ beta,
    __nv_bfloat16* __restrict__ outH, __nv_bfloat16* __restrict__ outL)
{
    __shared__ float red[8];
    const int t = blockIdx.x;
    const int tid = threadIdx.x;
    const float4 v = ((const float4*)(x + (size_t)t * Ee))[tid];

    float s = v.x + v.y + v.z + v.w;
    s = blockReduceSum(s, red);
    const float mu = s * (1.0f / Ee);

    float dx = (v.x-mu)*(v.x-mu) + (v.y-mu)*(v.y-mu) + (v.z-mu)*(v.z-mu) + (v.w-mu)*(v.w-mu);
    dx = blockReduceSum(dx, red);
    const float inv = rsqrtf(dx * (1.0f / Ee) + 1e-5f);

    const float4 g4 = ((const float4*)gamma)[tid];
    const float4 b4 = ((const float4*)beta)[tid];
    float r0 = (v.x - mu) * inv * g4.x + b4.x;
    float r1 = (v.y - mu) * inv * g4.y + b4.y;
    float r2 = (v.z - mu) * inv * g4.z + b4.z;
    float r3 = (v.w - mu) * inv * g4.w + b4.w;

    __nv_bfloat16 h0,h1,h2,h3,l0,l1,l2,l3;
    split_bf16(r0,h0,l0); split_bf16(r1,h1,l1);
    split_bf16(r2,h2,l2); split_bf16(r3,h3,l3);
    __nv_bfloat162 ph0; ph0.x=h0; ph0.y=h1;
    __nv_bfloat162 ph1; ph1.x=h2; ph1.y=h3;
    __nv_bfloat162 pl0; pl0.x=l0; pl0.y=l1;
    __nv_bfloat162 pl1; pl1.x=l2; pl1.y=l3;
    ((__nv_bfloat162*)(outH + (size_t)t * Ee))[2*tid]   = ph0;
    ((__nv_bfloat162*)(outH + (size_t)t * Ee))[2*tid+1] = ph1;
    ((__nv_bfloat162*)(outL + (size_t)t * Ee))[2*tid]   = pl0;
    ((__nv_bfloat162*)(outL + (size_t)t * Ee))[2*tid+1] = pl1;
}

// ------------------------- tensor-core GEMM (pre-split bf16 operands) ----------
// A: Ah/Al [M,K] bf16; B: Bh/Bl [N,K] bf16 (pre-transposed). Tile 128x128x32.
// smem per stage: 4 operands x 128 rows x 80B = 40960B; double buffered.
#define LDAU 20

__device__ __forceinline__ void ldsm4(uint32_t r[4], const uint32_t* p) {
    uint32_t addr = (uint32_t)__cvta_generic_to_shared(p);
    asm volatile("ldmatrix.sync.aligned.m8n8.x4.shared.b16 {%0,%1,%2,%3}, [%4];"
                 : "=r"(r[0]), "=r"(r[1]), "=r"(r[2]), "=r"(r[3]) : "r"(addr));
}

__device__ __forceinline__ void mma16816(float c[4], const uint32_t a[4],
                                         uint32_t b0, uint32_t b1) {
    asm volatile("mma.sync.aligned.m16n8k16.row.col.f32.bf16.bf16.f32 "
                 "{%0,%1,%2,%3}, {%4,%5,%6,%7}, {%8,%9}, {%0,%1,%2,%3};"
                 : "+f"(c[0]), "+f"(c[1]), "+f"(c[2]), "+f"(c[3])
                 : "r"(a[0]), "r"(a[1]), "r"(a[2]), "r"(a[3]), "r"(b0), "r"(b1));
}

__device__ __forceinline__ void cp_commit() { asm volatile("cp.async.commit_group;\n"); }
__device__ __forceinline__ void cp_wait1()  { asm volatile("cp.async.wait_group 1;\n"); }
__device__ __forceinline__ void cp_wait0()  { asm volatile("cp.async.wait_group 0;\n"); }

// issue one k-stage: 2048 16B chunks over 256 threads (8 each), coalesced per row
__device__ __forceinline__ void stage_issue(
    uint32_t sbase_st,
    const __nv_bfloat16* __restrict__ g0, const __nv_bfloat16* __restrict__ g1,
    const __nv_bfloat16* __restrict__ g2, const __nv_bfloat16* __restrict__ g3,
    int K, int k0, int tid)
{
    #pragma unroll
    for (int i = 0; i < 8; i++) {
        const int op  = i >> 1;
        const int row = ((i & 1) << 6) + (tid >> 2);
        const int c   = tid & 3;
        const __nv_bfloat16* gp =
            (op == 0 ? g0 : (op == 1 ? g1 : (op == 2 ? g2 : g3)));
        const __nv_bfloat16* g = gp + (size_t)row * K + k0 + c * 8;
        const uint32_t s = sbase_st + (uint32_t)(op * 10240 + row * 80 + c * 16);
        asm volatile("cp.async.cg.shared.global [%0], [%1], 16;\n" :: "r"(s), "l"(g));
    }
}

// shared -> fragments -> 3 mma passes (Ah*Bh + Ah*Bl + Al*Bh)
__device__ __forceinline__ void gemm_compute_stage(
    float (&acc)[2][8][4],
    const uint32_t* __restrict__ sAhS, const uint32_t* __restrict__ sAlS,
    const uint32_t* __restrict__ sBhS, const uint32_t* __restrict__ sBlS,
    int wm, int wn, int mrow, int koff)
{
    #pragma unroll
    for (int ks = 0; ks < 2; ks++) {
        uint32_t rAH[2][4];
        uint32_t rAL[2][4];
        uint32_t rBH[4][4];
        uint32_t rBL[4][4];
        #pragma unroll
        for (int mt = 0; mt < 2; mt++) {
            const int idx = (wm + mt * 16 + mrow) * LDAU + ks * 8 + koff;
            ldsm4(rAH[mt], sAhS + idx);
            ldsm4(rAL[mt], sAlS + idx);
        }
        #pragma unroll
        for (int p = 0; p < 4; p++) {
            const int idx = (wn + p * 16 + mrow) * LDAU + ks * 8 + koff;
            ldsm4(rBH[p], sBhS + idx);
            ldsm4(rBL[p], sBlS + idx);
        }
        #pragma unroll
        for (int mt = 0; mt < 2; mt++) {
            #pragma unroll
            for (int nt = 0; nt < 8; nt++) {
                const int p = nt >> 1;
                const int s = nt & 1;
                mma16816(acc[mt][nt], rAH[mt], rBH[p][s], rBH[p][s + 2]);
                mma16816(acc[mt][nt], rAH[mt], rBL[p][s], rBL[p][s + 2]);
                mma16816(acc[mt][nt], rAL[mt], rBH[p][s], rBH[p][s + 2]);
            }
        }
    }
}

// MODE 0: C = A*W + bias
// MODE 1: C = extra + A*W + bias
// MODE 2: C = gelu(A*W + bias)
// MODE 3: C = (A*W + bias) * extra
// OSPLIT: write Ch/Cl bf16 hi/lo instead of fp32 C
template<int MODE, int OSPLIT>
__global__ __launch_bounds__(256) void mma_gemm(
    const __nv_bfloat16* __restrict__ Ah, const __nv_bfloat16* __restrict__ Al,
    const __nv_bfloat16* __restrict__ Bh, const __nv_bfloat16* __restrict__ Bl,
    const float* __restrict__ bias, const float* __restrict__ extra,
    float* __restrict__ C,
    __nv_bfloat16* __restrict__ Ch, __nv_bfloat16* __restrict__ Cl,
    int M, int N, int K)
{
    extern __shared__ uint32_t sm_u[];
    const int tid  = threadIdx.x;
    const int lane = tid & 31;
    const int warp = tid >> 5;
    const int wm   = (warp & 3) * 32;
    const int wn   = (warp >> 2) * 64;
    const int bx   = blockIdx.x, by = blockIdx.y;

    float acc[2][8][4];
    #pragma unroll
    for (int i = 0; i < 2; i++)
        #pragma unroll
        for (int j = 0; j < 8; j++)
            #pragma unroll
            for (int q = 0; q < 4; q++) acc[i][j][q] = 0.f;

    const __nv_bfloat16* gA0 = Ah + (size_t)(by * 128) * K;
    const __nv_bfloat16* gA1 = Al + (size_t)(by * 128) * K;
    const __nv_bfloat16* gB0 = Bh + (size_t)(bx * 128) * K;
    const __nv_bfloat16* gB1 = Bl + (size_t)(bx * 128) * K;

    const uint32_t sbase = (uint32_t)__cvta_generic_to_shared(sm_u);
    const int mrow = (lane & 7) + ((lane >> 3) & 1) * 8;
    const int koff = (lane >> 4) * 4;

    stage_issue(sbase, gA0, gA1, gB0, gB1, K, 0, tid);
    cp_commit();

    const int nIter = K >> 5;
    for (int it = 0; it < nIter; ++it) {
        if (it + 1 < nIter) {
            stage_issue(sbase + ((it + 1) & 1) * 40960u,
                        gA0, gA1, gB0, gB1, K, (it + 1) << 5, tid);
            cp_commit();
            cp_wait1();
        } else {
            cp_wait0();
        }
        __syncthreads();
        const uint32_t* sp = sm_u + (it & 1) * 10240;
        gemm_compute_stage(acc, sp, sp + 2560, sp + 5120, sp + 7680,
                           wm, wn, mrow, koff);
        __syncthreads();
    }

    // ---- epilogue ----
    const int g  = lane >> 2;
    const int tg = lane & 3;
    #pragma unroll
    for (int mt = 0; mt < 2; mt++) {
        #pragma unroll
        for (int nt = 0; nt < 8; nt++) {
            const int col = bx * 128 + wn + nt * 8 + tg * 2;
            const float2 bi = *(const float2*)(bias + col);
            #pragma unroll
            for (int hf = 0; hf < 2; hf++) {
                const int row = by * 128 + wm + mt * 16 + g + hf * 8;
                const size_t off = (size_t)row * N + col;
                float rx = acc[mt][nt][hf * 2 + 0] + bi.x;
                float ry = acc[mt][nt][hf * 2 + 1] + bi.y;
                if (MODE == 1) {
                    const float2 e = *(const float2*)(extra + off);
                    rx += e.x; ry += e.y;
                }
                if (MODE == 2) {
                    rx = rx * normcdff(rx);
                    ry = ry * normcdff(ry);
                }
                if (MODE == 3) {
                    const float2 e = *(const float2*)(extra + off);
                    rx *= e.x; ry *= e.y;
                }
                if (OSPLIT) {
                    __nv_bfloat16 hx, lx, hy, ly;
                    split_bf16(rx, hx, lx);
                    split_bf16(ry, hy, ly);
                    __nv_bfloat162 ph; ph.x = hx; ph.y = hy;
                    __nv_bfloat162 pl; pl.x = lx; pl.y = ly;
                    *(__nv_bfloat162*)(Ch + off) = ph;
                    *(__nv_bfloat162*)(Cl + off) = pl;
                } else {
                    float2 r; r.x = rx; r.y = ry;
                    *(float2*)(C + off) = r;
                }
            }
        }
    }
}

// ------------------------- RoPE + split QKV -> [B,H,S,D] -------------------------
__global__ void rope_split_kernel(
    const float* __restrict__ qkv,
    float* __restrict__ Q, float* __restrict__ K, float* __restrict__ V)
{
    const int idx = blockIdx.x * blockDim.x + threadIdx.x;
    const int total = Bb * Hh * Ss * 32;
    if (idx >= total) return;
    const int dp = idx & 31;
    const int t  = idx >> 5;
    const int s  = t & (Ss - 1);
    const int bh = t >> 11;
    const int h  = bh & (Hh - 1);
    const int b  = bh >> 4;

    const float* base = qkv + (size_t)(b * Ss + s) * (3 * Ee) + h * Dd;
    const float q1 = base[dp],          q2 = base[dp + 32];
    const float k1 = base[Ee + dp],     k2 = base[Ee + dp + 32];
    const float v1 = base[2*Ee + dp],   v2 = base[2*Ee + dp + 32];

    const float inv = (float)exp(-(double)(2 * dp) / 64.0 * log(10000.0));
    const float ang = (float)s * inv;
    float sn, cs;
    sincosf(ang, &sn, &cs);

    const size_t o = ((size_t)bh * Ss + s) * Dd + dp;
    Q[o]      = q1 * cs - q2 * sn;
    Q[o + 32] = q2 * cs + q1 * sn;
    K[o]      = k1 * cs - k2 * sn;
    K[o + 32] = k2 * cs + k1 * sn;
    V[o]      = v1;
    V[o + 32] = v2;
}

// ------------------------- windowed flash attention (writes hi/lo bf16) --------
__global__ __launch_bounds__(256) void attn_kernel(
    const float* __restrict__ Qg, const float* __restrict__ Kg,
    const float* __restrict__ Vg,
    __nv_bfloat16* __restrict__ AOH, __nv_bfloat16* __restrict__ AOL)
{
    extern __shared__ float sm[];
    float* QsT = sm;
    float* Ks  = sm + 64 * 68;
    float* Vs  = Ks + 64 * 68;
    float* SsT = Vs + 64 * 68;

    const int tid = threadIdx.x;
    const int q0  = blockIdx.x * 64;
    const int bh  = blockIdx.y;
    const int b   = bh >> 4;
    const int h   = bh & (Hh - 1);
    const float* Qb = Qg + (size_t)bh * Ss * Dd;
    const float* Kb = Kg + (size_t)bh * Ss * Dd;
    const float* Vb = Vg + (size_t)bh * Ss * Dd;

    for (int p = tid; p < 1024; p += 256) {
        const int qr = p >> 4, d4 = (p & 15) << 2;
        const float4 v = *(const float4*)(Qb + (size_t)(q0 + qr) * Dd + d4);
        QsT[(d4+0)*68 + qr] = v.x;
        QsT[(d4+1)*68 + qr] = v.y;
        QsT[(d4+2)*68 + qr] = v.z;
        QsT[(d4+3)*68 + qr] = v.w;
    }

    const int ckey = tid >> 2;
    const int crg  = (tid & 3) << 4;
    const int srow = tid >> 2;
    const int sd0  = (tid & 3) << 4;

    float m = -1e30f, l = 0.f;
    float oacc[16];
    #pragma unroll
    for (int i = 0; i < 16; i++) oacc[i] = 0.f;

    __syncthreads();

    for (int c = 0; c < 5; c++) {
        const int kc0 = q0 - HALF_WIN + c * 64;
        for (int p = tid; p < 1024; p += 256) {
            const int kr = p >> 4, d4 = (p & 15) << 2;
            const int kg = kc0 + kr;
            float4 kv = make_float4(0.f, 0.f, 0.f, 0.f), vv = kv;
            if (kg >= 0 && kg < Ss) {
                kv = *(const float4*)(Kb + (size_t)kg * Dd + d4);
                vv = *(const float4*)(Vb + (size_t)kg * Dd + d4);
            }
            *(float4*)&Ks[kr * 68 + d4] = kv;
            *(float4*)&Vs[kr * 68 + d4] = vv;
        }
        __syncthreads();

        float sc[16];
        #pragma unroll
        for (int i = 0; i < 16; i++) sc[i] = 0.f;
        #pragma unroll 8
        for (int d = 0; d < 64; d++) {
            const float kval = Ks[ckey * 68 + d];
            const float4 qa  = *(const float4*)&QsT[d * 68 + crg];
            const float4 qb2 = *(const float4*)&QsT[d * 68 + crg + 4];
            const float4 qc  = *(const float4*)&QsT[d * 68 + crg + 8];
            const float4 qd  = *(const float4*)&QsT[d * 68 + crg + 12];
            sc[0]  += kval * qa.x;  sc[1]  += kval * qa.y;
            sc[2]  += kval * qa.z;  sc[3]  += kval * qa.w;
            sc[4]  += kval * qb2.x; sc[5]  += kval * qb2.y;
            sc[6]  += kval * qb2.z; sc[7]  += kval * qb2.w;
            sc[8]  += kval * qc.x;  sc[9]  += kval * qc.y;
            sc[10] += kval * qc.z;  sc[11] += kval * qc.w;
            sc[12] += kval * qd.x;  sc[13] += kval * qd.y;
            sc[14] += kval * qd.z;  sc[15] += kval * qd.w;
        }
        const int kg = kc0 + ckey;
        const bool kvalid = (kg >= 0 && kg < Ss);
        #pragma unroll
        for (int i = 0; i < 16; i++) {
            const int qg = q0 + crg + i;
            const bool ok = kvalid && (abs(qg - kg) <= HALF_WIN);
            SsT[ckey * 68 + crg + i] = ok ? sc[i] * 0.125f : -1e9f;
        }
        __syncthreads();

        float cmax = -1e30f;
        #pragma unroll 8
        for (int j = 0; j < 64; j++) cmax = fmaxf(cmax, SsT[j * 68 + srow]);
        if (cmax > -1e8f) {
            const float mnew = fmaxf(m, cmax);
            const float corr = __expf(m - mnew);
            m = mnew;
            l *= corr;
            #pragma unroll
            for (int i = 0; i < 16; i++) oacc[i] *= corr;
            #pragma unroll 4
            for (int j = 0; j < 64; j++) {
                const float p = __expf(SsT[j * 68 + srow] - m);
                l += p;
                const float4 v0 = *(const float4*)&Vs[j * 68 + sd0];
                const float4 v1 = *(const float4*)&Vs[j * 68 + sd0 + 4];
                const float4 v2 = *(const float4*)&Vs[j * 68 + sd0 + 8];
                const float4 v3 = *(const float4*)&Vs[j * 68 + sd0 + 12];
                oacc[0]  += p * v0.x; oacc[1]  += p * v0.y;
                oacc[2]  += p * v0.z; oacc[3]  += p * v0.w;
                oacc[4]  += p * v1.x; oacc[5]  += p * v1.y;
                oacc[6]  += p * v1.z; oacc[7]  += p * v1.w;
                oacc[8]  += p * v2.x; oacc[9]  += p * v2.y;
                oacc[10] += p * v2.z; oacc[11] += p * v2.w;
                oacc[12] += p * v3.x; oacc[13] += p * v3.y;
                oacc[14] += p * v3.z; oacc[15] += p * v3.w;
            }
        }
        __syncthreads();
    }

    const float inv = 1.0f / l;
    const size_t obase = (size_t)(b * Ss + q0 + srow) * Ee + h * Dd + sd0;
    #pragma unroll
    for (int gq = 0; gq < 4; gq++) {
        float v0 = oacc[gq*4+0] * inv;
        float v1 = oacc[gq*4+1] * inv;
        float v2 = oacc[gq*4+2] * inv;
        float v3 = oacc[gq*4+3] * inv;
        __nv_bfloat16 h0,h1,h2,h3,l0,l1,l2,l3;
        split_bf16(v0,h0,l0); split_bf16(v1,h1,l1);
        split_bf16(v2,h2,l2); split_bf16(v3,h3,l3);
        __nv_bfloat162 ph0; ph0.x=h0; ph0.y=h1;
        __nv_bfloat162 ph1; ph1.x=h2; ph1.y=h3;
        __nv_bfloat162 pl0; pl0.x=l0; pl0.y=l1;
        __nv_bfloat162 pl1; pl1.x=l2; pl1.y=l3;
        ((__nv_bfloat162*)(AOH + obase + gq * 4))[0] = ph0;
        ((__nv_bfloat162*)(AOH + obase + gq * 4))[1] = ph1;
        ((__nv_bfloat162*)(AOL + obase + gq * 4))[0] = pl0;
        ((__nv_bfloat162*)(AOL + obase + gq * 4))[1] = pl1;
    }
}

// ------------------------- launch -------------------------
extern "C" void kernel_launch(void* const* d_in, const int* in_sizes, int n_in,
                              void* d_out, int out_size)
{
    (void)in_sizes; (void)n_in; (void)out_size;
    const float* src    = (const float*)d_in[0];
    const float* Wqkv   = (const float*)d_in[1];
    const float* bqkv   = (const float*)d_in[2];
    const float* Wout   = (const float*)d_in[3];
    const float* bout   = (const float*)d_in[4];
    const float* gamma1 = (const float*)d_in[5];
    const float* beta1  = (const float*)d_in[6];
    const float* gamma2 = (const float*)d_in[7];
    const float* beta2  = (const float*)d_in[8];
    const float* Wg     = (const float*)d_in[9];
    const float* bg     = (const float*)d_in[10];
    const float* Wv     = (const float*)d_in[11];
    const float* bv     = (const float*)d_in[12];
    const float* Wo     = (const float*)d_in[13];
    const float* bo     = (const float*)d_in[14];

    float *qkv, *q, *k, *v, *x1, *gelu;
    __nv_bfloat16 *hH, *hL, *attnH, *attnL, *gateH, *gateL;
    __nv_bfloat16 *WqkvTh, *WqkvTl, *WoutTh, *WoutTl, *WgTh, *WgTl, *WvTh, *WvTl, *WoTh, *WoTl;
    cudaGetSymbolAddress((void**)&qkv,   g_qkv);
    cudaGetSymbolAddress((void**)&q,     g_q);
    cudaGetSymbolAddress((void**)&k,     g_k);
    cudaGetSymbolAddress((void**)&v,     g_v);
    cudaGetSymbolAddress((void**)&x1,    g_x1);
    cudaGetSymbolAddress((void**)&gelu,  g_gelu);
    cudaGetSymbolAddress((void**)&hH,    g_hH);
    cudaGetSymbolAddress((void**)&hL,    g_hL);
    cudaGetSymbolAddress((void**)&attnH, g_attnH);
    cudaGetSymbolAddress((void**)&attnL, g_attnL);
    cudaGetSymbolAddress((void**)&gateH, g_gateH);
    cudaGetSymbolAddress((void**)&gateL, g_gateL);
    cudaGetSymbolAddress((void**)&WqkvTh, g_WqkvTh);
    cudaGetSymbolAddress((void**)&WqkvTl, g_WqkvTl);
    cudaGetSymbolAddress((void**)&WoutTh, g_WoutTh);
    cudaGetSymbolAddress((void**)&WoutTl, g_WoutTl);
    cudaGetSymbolAddress((void**)&WgTh,  g_WgTh);
    cudaGetSymbolAddress((void**)&WgTl,  g_WgTl);
    cudaGetSymbolAddress((void**)&WvTh,  g_WvTh);
    cudaGetSymbolAddress((void**)&WvTl,  g_WvTl);
    cudaGetSymbolAddress((void**)&WoTh,  g_WoTh);
    cudaGetSymbolAddress((void**)&WoTl,  g_WoTl);

    const int ATTN_SMEM = 4 * 64 * 68 * 4;  // 69632 B
    cudaFuncSetAttribute(attn_kernel, cudaFuncAttributeMaxDynamicSharedMemorySize, ATTN_SMEM);
    const int GEMM_SMEM = 2 * 40960;        // 81920 B
    cudaFuncSetAttribute((const void*)mma_gemm<0,0>, cudaFuncAttributeMaxDynamicSharedMemorySize, GEMM_SMEM);
    cudaFuncSetAttribute((const void*)mma_gemm<1,0>, cudaFuncAttributeMaxDynamicSharedMemorySize, GEMM_SMEM);
    cudaFuncSetAttribute((const void*)mma_gemm<2,0>, cudaFuncAttributeMaxDynamicSharedMemorySize, GEMM_SMEM);
    cudaFuncSetAttribute((const void*)mma_gemm<3,1>, cudaFuncAttributeMaxDynamicSharedMemorySize, GEMM_SMEM);

    // 0) weight transpose + split (once per launch; ~20us)
    wsplit_kernel<<<dim3(3 * Ee / 32, Ee / 32), 256>>>(Wqkv, WqkvTh, WqkvTl, Ee, 3 * Ee);
    wsplit_kernel<<<dim3(Ee / 32, Ee / 32), 256>>>(Wout, WoutTh, WoutTl, Ee, Ee);
    wsplit_kernel<<<dim3(FFf / 32, Ee / 32), 256>>>(Wg, WgTh, WgTl, Ee, FFf);
    wsplit_kernel<<<dim3(FFf / 32, Ee / 32), 256>>>(Wv, WvTh, WvTl, Ee, FFf);
    wsplit_kernel<<<dim3(Ee / 32, FFf / 32), 256>>>(Wo, WoTh, WoTl, FFf, Ee);

    // 1) h1 = LN(src) -> hi/lo bf16
    ln_kernel<<<NT, 256>>>(src, gamma1, beta1, hH, hL);

    // 2) qkv = h1 @ Wqkv + bqkv (fp32 out)
    mma_gemm<0,0><<<dim3(3 * Ee / 128, NT / 128), 256, GEMM_SMEM>>>(
        hH, hL, WqkvTh, WqkvTl, bqkv, nullptr, qkv, nullptr, nullptr, NT, 3 * Ee, Ee);

    // 3) RoPE + split
    {
        const int total = Bb * Hh * Ss * 32;
        rope_split_kernel<<<(total + 255) / 256, 256>>>(qkv, q, k, v);
    }

    // 4) windowed attention -> hi/lo bf16 [NT, E]
    attn_kernel<<<dim3(Ss / 64, Bb * Hh), 256, ATTN_SMEM>>>(q, k, v, attnH, attnL);

    // 5) x1 = src + attn @ Wout + bout (fp32)
    mma_gemm<1,0><<<dim3(Ee / 128, NT / 128), 256, GEMM_SMEM>>>(
        attnH, attnL, WoutTh, WoutTl, bout, src, x1, nullptr, nullptr, NT, Ee, Ee);

    // 6) h2 = LN(x1) -> hi/lo bf16
    ln_kernel<<<NT, 256>>>(x1, gamma2, beta2, hH, hL);

    // 7) gelu = gelu(h2 @ Wg + bg) (fp32)
    mma_gemm<2,0><<<dim3(FFf / 128, NT / 128), 256, GEMM_SMEM>>>(
        hH, hL, WgTh, WgTl, bg, nullptr, gelu, nullptr, nullptr, NT, FFf, Ee);

    // 8) gate = (h2 @ Wv + bv) * gelu -> hi/lo bf16
    mma_gemm<3,1><<<dim3(FFf / 128, NT / 128), 256, GEMM_SMEM>>>(
        hH, hL, WvTh, WvTl, bv, gelu, nullptr, gateH, gateL, NT, FFf, Ee);

    // 9) out = x1 + gate @ Wo + bo (fp32)
    mma_gemm<1,0><<<dim3(Ee / 128, NT / 128), 256, GEMM_SMEM>>>(
        gateH, gateL, WoTh, WoTl, bo, x1, (float*)d_out, nullptr, nullptr, NT, Ee, FFf);
}